// round 17
// baseline (speedup 1.0000x reference)
#include <cuda_runtime.h>
#include <math.h>

#define BATCH 1024
#define NTOK  64
#define CDIM  256
#define HEADS 8
#define HDIM  32
#define NWIN  64
#define QKVN  768

// ---------------- scratch (device globals; no allocations) ----------------
__device__ float g_qkv[BATCH * NTOK * QKVN];   // (b*64+t, 768) row-major
__device__ float g_ctx[BATCH * NTOK * CDIM];   // (b*64+t, 256) row-major
__device__ float g_rpb[HEADS * NTOK * NTOK];   // (h, p, q)

// ---------------- relative position bias (MLP + gather + sigmoid) ----------
__global__ __launch_bounds__(256) void rpb_kernel(
    const float* __restrict__ w1, const float* __restrict__ b1,
    const float* __restrict__ w2)
{
    __shared__ float hbt[225][8];
    int tid = threadIdx.x;
    if (tid < 225) {
        int i = tid / 15, j = tid % 15;
        float ri = (float)(i - 7) * (8.0f / 7.0f);
        float rj = (float)(j - 7) * (8.0f / 7.0f);
        float t0 = copysignf(log2f(fabsf(ri) + 1.0f) * (1.0f / 3.0f), ri);
        float t1 = copysignf(log2f(fabsf(rj) + 1.0f) * (1.0f / 3.0f), rj);
        if (ri == 0.0f) t0 = 0.0f;
        if (rj == 0.0f) t1 = 0.0f;
        float acc[8];
        #pragma unroll
        for (int h = 0; h < 8; h++) acc[h] = 0.0f;
        for (int u = 0; u < 512; u++) {
            float hv = fmaxf(t0 * w1[2 * u] + t1 * w1[2 * u + 1] + b1[u], 0.0f);
            #pragma unroll
            for (int h = 0; h < 8; h++) acc[h] += hv * w2[h * 512 + u];
        }
        #pragma unroll
        for (int h = 0; h < 8; h++) hbt[tid][h] = acc[h];
    }
    __syncthreads();
    for (int idx = tid; idx < HEADS * NTOK * NTOK; idx += 256) {
        int h = idx >> 12;
        int p = (idx >> 6) & 63;
        int q = idx & 63;
        int dy = (p >> 3) - (q >> 3) + 7;
        int dx = (p & 7) - (q & 7) + 7;
        float v = hbt[dy * 15 + dx][h];
        g_rpb[idx] = 16.0f / (1.0f + expf(-v));
    }
}

// -------- fp32x2 SGEMM (R13 version — at the fp32 rt=2 roofline; FROZEN) ---
#define BM 128
#define BNT 64
#define BK 16

__device__ __forceinline__ float get_bias(int n, const float* b0,
                                          const float* b1, int mode)
{
    if (mode) return b0[n];
    if (n < 256) return b0[n];
    if (n < 512) return 0.0f;
    return b1[n - 512];
}

__device__ __forceinline__ void sgemm_body(
    const float* __restrict__ A, const float* __restrict__ B,
    float* __restrict__ C, int N,
    const float* __restrict__ bias0, const float* __restrict__ bias1, int mode)
{
    const int K = 256;
    __shared__ float As[BK][BM];   // 8 KB
    __shared__ float Bs[BK][BNT];  // 4 KB
    int tid = threadIdx.x;
    int mBase = blockIdx.y * BM;
    int nBase = blockIdx.x * BNT;
    int ty = tid >> 4, tx = tid & 15;

    unsigned long long acc2[4][4];
    #pragma unroll
    for (int i = 0; i < 4; i++)
        #pragma unroll
        for (int j = 0; j < 4; j++) acc2[i][j] = 0ULL;

    int arow0 = tid >> 2;
    int arow1 = arow0 + 64;
    int ak4   = (tid & 3) << 2;
    int brow  = tid >> 2;
    int bk4   = (tid & 3) << 2;

    for (int kt = 0; kt < K; kt += BK) {
        {
            float4 a0 = *(const float4*)&A[(size_t)(mBase + arow0) * K + kt + ak4];
            float4 a1 = *(const float4*)&A[(size_t)(mBase + arow1) * K + kt + ak4];
            float4 vb = *(const float4*)&B[(size_t)(nBase + brow) * K + kt + bk4];
            As[ak4 + 0][arow0] = a0.x; As[ak4 + 1][arow0] = a0.y;
            As[ak4 + 2][arow0] = a0.z; As[ak4 + 3][arow0] = a0.w;
            As[ak4 + 0][arow1] = a1.x; As[ak4 + 1][arow1] = a1.y;
            As[ak4 + 2][arow1] = a1.z; As[ak4 + 3][arow1] = a1.w;
            Bs[bk4 + 0][brow] = vb.x; Bs[bk4 + 1][brow] = vb.y;
            Bs[bk4 + 2][brow] = vb.z; Bs[bk4 + 3][brow] = vb.w;
        }
        __syncthreads();
        #pragma unroll
        for (int kk = 0; kk < BK; kk++) {
            unsigned long long a2[4];
            *(ulonglong2*)&a2[0] = *(const ulonglong2*)&As[kk][ty * 8];
            *(ulonglong2*)&a2[2] = *(const ulonglong2*)&As[kk][ty * 8 + 4];
            float b[4];
            *(float4*)&b[0] = *(const float4*)&Bs[kk][tx * 4];
            #pragma unroll
            for (int j = 0; j < 4; j++) {
                unsigned long long b2;
                asm("mov.b64 %0, {%1, %1};" : "=l"(b2) : "f"(b[j]));
                #pragma unroll
                for (int ip = 0; ip < 4; ip++)
                    asm("fma.rn.f32x2 %0, %1, %2, %0;"
                        : "+l"(acc2[ip][j]) : "l"(a2[ip]), "l"(b2));
            }
        }
        __syncthreads();
    }

    int n = nBase + tx * 4;
    float b0v = get_bias(n + 0, bias0, bias1, mode);
    float b1v = get_bias(n + 1, bias0, bias1, mode);
    float b2v = get_bias(n + 2, bias0, bias1, mode);
    float b3v = get_bias(n + 3, bias0, bias1, mode);
    #pragma unroll
    for (int ip = 0; ip < 4; ip++) {
        float r0[4], r1[4];
        #pragma unroll
        for (int j = 0; j < 4; j++)
            asm("mov.b64 {%0, %1}, %2;"
                : "=f"(r0[j]), "=f"(r1[j]) : "l"(acc2[ip][j]));
        int m0 = mBase + ty * 8 + 2 * ip;
        float4 v0, v1;
        v0.x = r0[0] + b0v; v0.y = r0[1] + b1v;
        v0.z = r0[2] + b2v; v0.w = r0[3] + b3v;
        v1.x = r1[0] + b0v; v1.y = r1[1] + b1v;
        v1.z = r1[2] + b2v; v1.w = r1[3] + b3v;
        *(float4*)&C[(size_t)m0 * N + n] = v0;
        *(float4*)&C[(size_t)(m0 + 1) * N + n] = v1;
    }
}

__global__ __launch_bounds__(256, 3) void qkv_gemm_kernel(
    const float* __restrict__ x, const float* __restrict__ w,
    const float* __restrict__ qb, const float* __restrict__ vb)
{
    sgemm_body(x, w, g_qkv, QKVN, qb, vb, 0);
}

__global__ __launch_bounds__(256, 3) void proj_gemm_kernel(
    const float* __restrict__ w, float* __restrict__ out,
    const float* __restrict__ pb)
{
    sgemm_body(g_ctx, w, out, CDIM, pb, nullptr, 1);
}

// -------- per-(window,head) attention — fused norm+QK+softmax --------------
__global__ __launch_bounds__(256) void attn_kernel(
    const float* __restrict__ mask, const float* __restrict__ logit_scale)
{
    __shared__ float qs[HDIM][68];     // transposed [d][t]
    __shared__ float ks[HDIM][68];
    __shared__ float vs[NTOK][HDIM];   // [t][d]
    __shared__ float sm[NTOK][68];     // probabilities
    __shared__ float invq[64], invk[64];

    int b = blockIdx.x >> 3;
    int h = blockIdx.x & 7;
    int tid = threadIdx.x;

    // float4 global loads: 512 float4 per matrix, 2 per thread
    #pragma unroll
    for (int r = 0; r < 2; r++) {
        int idx = tid + r * 256;              // 0..511
        int t = idx >> 3, d4 = (idx & 7) << 2;
        size_t base = (size_t)(b * NTOK + t) * QKVN + h * HDIM + d4;
        float4 qv = *(const float4*)&g_qkv[base];
        float4 kv = *(const float4*)&g_qkv[base + CDIM];
        float4 vv = *(const float4*)&g_qkv[base + 2 * CDIM];
        qs[d4 + 0][t] = qv.x; qs[d4 + 1][t] = qv.y;
        qs[d4 + 2][t] = qv.z; qs[d4 + 3][t] = qv.w;
        ks[d4 + 0][t] = kv.x; ks[d4 + 1][t] = kv.y;
        ks[d4 + 2][t] = kv.z; ks[d4 + 3][t] = kv.w;
        *(float4*)&vs[t][d4] = vv;
    }
    __syncthreads();

    // compute inverse norms only (no smem rewrite)
    if (tid < 128) {
        int t = tid & 63;
        float (*arr)[68] = (tid < 64) ? qs : ks;
        float ss = 0.0f;
        #pragma unroll
        for (int d = 0; d < HDIM; d++) { float v = arr[d][t]; ss += v * v; }
        float inv = 1.0f / fmaxf(sqrtf(ss), 1e-12f);
        ((tid < 64) ? invq : invk)[t] = inv;
    }
    __syncthreads();

    float scale = __expf(fminf(logit_scale[h], 4.605170185988091f)); // ln(100)
    int wmask = b & (NWIN - 1);

    // fused: S = q@k^T (raw) -> scale by invq*invk -> +rpb+mask -> softmax
    // (row reductions via shfl over lane bits 0-3; probs written once)
    {
        int trow = tid >> 4, tcol = tid & 15;
        float s4[4][4];
        #pragma unroll
        for (int i = 0; i < 4; i++)
            #pragma unroll
            for (int j = 0; j < 4; j++) s4[i][j] = 0.0f;
        #pragma unroll
        for (int d = 0; d < HDIM; d++) {
            float4 a = *(const float4*)&qs[d][trow * 4];
            float4 bb = *(const float4*)&ks[d][tcol * 4];
            float av[4] = {a.x, a.y, a.z, a.w};
            float bv[4] = {bb.x, bb.y, bb.z, bb.w};
            #pragma unroll
            for (int i = 0; i < 4; i++)
                #pragma unroll
                for (int j = 0; j < 4; j++) s4[i][j] += av[i] * bv[j];
        }
        float4 ivk4 = *(const float4*)&invk[tcol * 4];
        float ivk[4] = {ivk4.x, ivk4.y, ivk4.z, ivk4.w};
        #pragma unroll
        for (int i = 0; i < 4; i++) {
            int p = trow * 4 + i;
            float ivqs = invq[p] * scale;
            float4 rv = *(const float4*)&g_rpb[(h * NTOK + p) * NTOK + tcol * 4];
            float4 mv = *(const float4*)&mask[((size_t)wmask * NTOK + p) * NTOK + tcol * 4];
            float v0 = s4[i][0] * ivqs * ivk[0] + rv.x + mv.x;
            float v1 = s4[i][1] * ivqs * ivk[1] + rv.y + mv.y;
            float v2 = s4[i][2] * ivqs * ivk[2] + rv.z + mv.z;
            float v3 = s4[i][3] * ivqs * ivk[3] + rv.w + mv.w;
            // row softmax across the 16 tcol lanes (lane bits 0-3)
            float mx = fmaxf(fmaxf(v0, v1), fmaxf(v2, v3));
            mx = fmaxf(mx, __shfl_xor_sync(0xffffffffu, mx, 1));
            mx = fmaxf(mx, __shfl_xor_sync(0xffffffffu, mx, 2));
            mx = fmaxf(mx, __shfl_xor_sync(0xffffffffu, mx, 4));
            mx = fmaxf(mx, __shfl_xor_sync(0xffffffffu, mx, 8));
            v0 = __expf(v0 - mx); v1 = __expf(v1 - mx);
            v2 = __expf(v2 - mx); v3 = __expf(v3 - mx);
            float sum = (v0 + v1) + (v2 + v3);
            sum += __shfl_xor_sync(0xffffffffu, sum, 1);
            sum += __shfl_xor_sync(0xffffffffu, sum, 2);
            sum += __shfl_xor_sync(0xffffffffu, sum, 4);
            sum += __shfl_xor_sync(0xffffffffu, sum, 8);
            float inv = 1.0f / sum;
            *(float4*)&sm[p][tcol * 4] =
                make_float4(v0 * inv, v1 * inv, v2 * inv, v3 * inv);
        }
    }
    __syncthreads();

    // O = S @ V : vectorized over m (4 m-values per iteration)
    {
        int r2 = tid >> 3;            // 0..31 -> rows 2*r2, 2*r2+1
        int c4 = (tid & 7) * 4;       // 0..28
        int row0 = r2 * 2;
        float o0[4] = {0.f, 0.f, 0.f, 0.f};
        float o1[4] = {0.f, 0.f, 0.f, 0.f};
        #pragma unroll 4
        for (int m = 0; m < NTOK; m += 4) {
            float4 s0 = *(const float4*)&sm[row0][m];
            float4 s1 = *(const float4*)&sm[row0 + 1][m];
            float4 va = *(const float4*)&vs[m + 0][c4];
            float4 vb = *(const float4*)&vs[m + 1][c4];
            float4 vc = *(const float4*)&vs[m + 2][c4];
            float4 vd = *(const float4*)&vs[m + 3][c4];
            o0[0] += s0.x * va.x + s0.y * vb.x + s0.z * vc.x + s0.w * vd.x;
            o0[1] += s0.x * va.y + s0.y * vb.y + s0.z * vc.y + s0.w * vd.y;
            o0[2] += s0.x * va.z + s0.y * vb.z + s0.z * vc.z + s0.w * vd.z;
            o0[3] += s0.x * va.w + s0.y * vb.w + s0.z * vc.w + s0.w * vd.w;
            o1[0] += s1.x * va.x + s1.y * vb.x + s1.z * vc.x + s1.w * vd.x;
            o1[1] += s1.x * va.y + s1.y * vb.y + s1.z * vc.y + s1.w * vd.y;
            o1[2] += s1.x * va.z + s1.y * vb.z + s1.z * vc.z + s1.w * vd.z;
            o1[3] += s1.x * va.w + s1.y * vb.w + s1.z * vc.w + s1.w * vd.w;
        }
        size_t obase = (size_t)(b * NTOK + row0) * CDIM + h * HDIM + c4;
        *(float4*)&g_ctx[obase] = make_float4(o0[0], o0[1], o0[2], o0[3]);
        *(float4*)&g_ctx[obase + CDIM] = make_float4(o1[0], o1[1], o1[2], o1[3]);
    }
}

// ---------------- entry ----------------------------------------------------
extern "C" void kernel_launch(void* const* d_in, const int* in_sizes, int n_in,
                              void* d_out, int out_size)
{
    (void)in_sizes; (void)n_in; (void)out_size;
    const float* x           = (const float*)d_in[0];
    const float* mask        = (const float*)d_in[1];
    const float* qkv_w       = (const float*)d_in[2];
    const float* q_bias      = (const float*)d_in[3];
    const float* v_bias      = (const float*)d_in[4];
    const float* logit_scale = (const float*)d_in[5];
    const float* mlp_w1      = (const float*)d_in[6];
    const float* mlp_b1      = (const float*)d_in[7];
    const float* mlp_w2      = (const float*)d_in[8];
    const float* proj_w      = (const float*)d_in[9];
    const float* proj_b      = (const float*)d_in[10];
    float* out = (float*)d_out;

    rpb_kernel<<<1, 256>>>(mlp_w1, mlp_b1, mlp_w2);

    dim3 qkv_grid(QKVN / BNT, (BATCH * NTOK) / BM);   // (12, 512)
    qkv_gemm_kernel<<<qkv_grid, 256>>>(x, qkv_w, q_bias, v_bias);

    attn_kernel<<<BATCH * HEADS, 256>>>(mask, logit_scale);

    dim3 proj_grid(CDIM / BNT, (BATCH * NTOK) / BM);  // (4, 512)
    proj_gemm_kernel<<<proj_grid, 256>>>(proj_w, out, proj_b);
}